// round 16
// baseline (speedup 1.0000x reference)
#include <cuda_runtime.h>
#include <cuda_bf16.h>

#define SENS 61
#define HID  64
#define NSTEPS 10
#define TPB  128

typedef unsigned long long u64;
typedef unsigned int u32;

// Dormand–Prince 5(4) tableau
__constant__ float c_A[6][5] = {
  {0.f, 0.f, 0.f, 0.f, 0.f},
  {(float)(1.0/5.0), 0.f, 0.f, 0.f, 0.f},
  {(float)(3.0/40.0), (float)(9.0/40.0), 0.f, 0.f, 0.f},
  {(float)(44.0/45.0), (float)(-56.0/15.0), (float)(32.0/9.0), 0.f, 0.f},
  {(float)(19372.0/6561.0), (float)(-25360.0/2187.0), (float)(64448.0/6561.0), (float)(-212.0/729.0), 0.f},
  {(float)(9017.0/3168.0), (float)(-355.0/33.0), (float)(46732.0/5247.0), (float)(49.0/176.0), (float)(-5103.0/18656.0)}
};
__constant__ float c_C[6] = {0.f, 0.2f, 0.3f, 0.8f, (float)(8.0/9.0), 1.f};
__constant__ float c_Bw[6] = {(float)(35.0/384.0), 0.f, (float)(500.0/1113.0),
                              (float)(125.0/192.0), (float)(-2187.0/6784.0), (float)(11.0/84.0)};

// ---- helpers ----
__device__ __forceinline__ float ftanh(float x) {
  float r; asm("tanh.approx.f32 %0, %1;" : "=f"(r) : "f"(x)); return r;
}
__device__ __forceinline__ u32 f16x2_of(float lo, float hi) {
  u32 r; asm("cvt.rn.f16x2.f32 %0, %1, %2;" : "=r"(r) : "f"(hi), "f"(lo)); return r; // upper=hi, lower=lo
}
__device__ __forceinline__ u32 tanh2(u32 x) {
  u32 r; asm("tanh.approx.f16x2 %0, %1;" : "=r"(r) : "r"(x)); return r;
}
__device__ __forceinline__ u32 smem_u32(const void* p) {
  u32 a; asm("{ .reg .u64 t; cvta.to.shared.u64 t, %1; cvt.u32.u64 %0, t; }" : "=r"(a) : "l"(p));
  return a;
}
__device__ __forceinline__ void ldmx2(u32& r0, u32& r1, u32 addr) {
  asm volatile("ldmatrix.sync.aligned.m8n8.x2.shared.b16 {%0,%1}, [%2];"
               : "=r"(r0), "=r"(r1) : "r"(addr));
}
// m16n8k8, f16 in/out: D = A*B + C  (C separate, f16x2 pairs)
__device__ __forceinline__ void mma_k8_f16(u32& d0, u32& d1,
                                           u32 a0, u32 a1, u32 b0, u32 c0, u32 c1) {
  asm volatile("mma.sync.aligned.m16n8k8.row.col.f16.f16.f16.f16 "
               "{%0,%1}, {%2,%3}, {%4}, {%5,%6};"
               : "=r"(d0), "=r"(d1)
               : "r"(a0), "r"(a1), "r"(b0), "r"(c0), "r"(c1));
}
// m16n8k16, f32 acc, in-place C=D
__device__ __forceinline__ void mmaf16(float& d0, float& d1, float& d2, float& d3,
                                       u32 a0, u32 a1, u32 a2, u32 a3, u32 b0, u32 b1) {
  asm volatile("mma.sync.aligned.m16n8k16.row.col.f32.f16.f16.f32 "
               "{%0,%1,%2,%3}, {%4,%5,%6,%7}, {%8,%9}, {%0,%1,%2,%3};"
               : "+f"(d0), "+f"(d1), "+f"(d2), "+f"(d3)
               : "r"(a0), "r"(a1), "r"(a2), "r"(a3), "r"(b0), "r"(b1));
}
// m16n8k16, f32 acc, separate C (accumulator init for free)
__device__ __forceinline__ void mmaf16_c(float& d0, float& d1, float& d2, float& d3,
                                         u32 a0, u32 a1, u32 a2, u32 a3, u32 b0, u32 b1,
                                         float c0, float c1, float c2, float c3) {
  asm volatile("mma.sync.aligned.m16n8k16.row.col.f32.f16.f16.f32 "
               "{%0,%1,%2,%3}, {%4,%5,%6,%7}, {%8,%9}, {%10,%11,%12,%13};"
               : "=f"(d0), "=f"(d1), "=f"(d2), "=f"(d3)
               : "r"(a0), "r"(a1), "r"(a2), "r"(a3), "r"(b0), "r"(b1),
                 "f"(c0), "f"(c1), "f"(c2), "f"(c3));
}

// smem byte offsets
#define OFF_X    0                          // 4 warps * 32 rows * 16B = 2048 (x = [y,t] f16, k-pad 8)
#define OFF_S1F  2048                       // uint4[8 (m*4+kk)][TPB] = 16384 (s1 in D1-fragment layout)
#define OFF_BF   (OFF_S1F + 16384)          // uint4[4 kk][4 jp][32 lane] = 8192 (W2 B-frags, f16)
#define OFF_B2F  (OFF_BF + 8192)            // float4[4 t][4 q] = 256 (b2 fragments)
#define OFF_W3F  (OFF_B2F + 256)            // uint2[4 kk2][32 lane] = 1024 (W3 B-frags, f16, N-pad 8)
#define OFF_W1B  (OFF_W3F + 1024)           // uint2[4 kk][32 lane] = 1024 (W1 y/t B-frags, k-pad 8)
#define OFF_STG  (OFF_W1B + 1024)           // 4 warps * 32 * 16B = 2048 (result staging)
#define SMEM_BYTES (OFF_STG + 2048)         // 30976

__global__ void __launch_bounds__(TPB, 3)
ode_kernel(const float* __restrict__ pad0, const float* __restrict__ sens,
           const float* __restrict__ W1, const float* __restrict__ b1,
           const float* __restrict__ W2, const float* __restrict__ b2,
           const float* __restrict__ W3, const float* __restrict__ b3,
           const float* __restrict__ scale, float* __restrict__ out, int nrows)
{
  extern __shared__ char smem[];
  const u32 smem_base = smem_u32(smem);
  const int tid  = threadIdx.x;
  const int lane = tid & 31;
  const int wid  = tid >> 5;
  const int g    = lane >> 2;     // fragment group id (row within 8)
  const int t    = lane & 3;      // thread-in-group (col pair)

  const float4* sB2Fq = (const float4*)(smem + OFF_B2F);

  // ---- cooperative weight staging ----
  // W1 y/t B-fragments for m16n8k8 (k = [y0,y1,y2,t,0,0,0,0]):
  // b0(j) = f16x2(W1y[2t][8j+g], W1y[2t+1][8j+g]); rows >=4 are zero.
  if (tid < 32) {
    int gl = tid >> 2, tl = tid & 3;
    #pragma unroll
    for (int jp = 0; jp < 4; jp++) {
      u32 v[2];
      #pragma unroll
      for (int e = 0; e < 2; e++) {
        int n = 8*(2*jp + e) + gl;
        float wa = 0.f, wb = 0.f;
        if (tl == 0)      { wa = __ldg(W1 + 0*HID + n);  wb = __ldg(W1 + 1*HID + n);  }
        else if (tl == 1) { wa = __ldg(W1 + 2*HID + n);  wb = __ldg(W1 + 64*HID + n); }
        v[e] = f16x2_of(wa, wb);
      }
      *(uint2*)(smem + OFF_W1B + (jp*32 + tid)*8) = make_uint2(v[0], v[1]);
    }
  }
  // W2 B-fragments (f16), per-lane layout, one copy for all warps
  if (tid < 32) {
    int gl = tid >> 2, tl = tid & 3;
    #pragma unroll
    for (int kk = 0; kk < 4; kk++) {
      #pragma unroll
      for (int jp = 0; jp < 4; jp++) {
        u32 v[4];
        #pragma unroll
        for (int e = 0; e < 2; e++) {     // j = 2*jp + e
          int n = 8*(2*jp + e) + gl;
          int k0 = 16*kk + 2*tl;
          v[2*e + 0] = f16x2_of(__ldg(W2 + (k0    )*HID + n), __ldg(W2 + (k0 + 1)*HID + n));
          v[2*e + 1] = f16x2_of(__ldg(W2 + (k0 + 8)*HID + n), __ldg(W2 + (k0 + 9)*HID + n));
        }
        *(uint4*)(smem + OFF_BF + (((kk*4 + jp)*32) + tid)*16) = make_uint4(v[0], v[1], v[2], v[3]);
      }
    }
  }
  // b2 fragments: [t][q] = {b2[16q+2t], b2[16q+2t+1], b2[16q+8+2t], b2[16q+8+2t+1]}
  if (tid < 16) {
    int tt = tid >> 2, q = tid & 3;
    *(float4*)(smem + OFF_B2F + tid*16) =
      make_float4(__ldg(b2 + 16*q + 2*tt),     __ldg(b2 + 16*q + 2*tt + 1),
                  __ldg(b2 + 16*q + 8 + 2*tt), __ldg(b2 + 16*q + 8 + 2*tt + 1));
  }
  // W3 B-fragments (f16): 4 k-blocks of 16; B tile 16(k) x 8(n), n>=3 zero-padded
  if (tid < 32) {
    int gl = tid >> 2, tl = tid & 3;
    #pragma unroll
    for (int kk2 = 0; kk2 < 4; kk2++) {
      int k0 = kk2*16 + 2*tl;
      float w0a = (gl < 3) ? __ldg(W3 + (k0    )*3 + gl) : 0.0f;
      float w0b = (gl < 3) ? __ldg(W3 + (k0 + 1)*3 + gl) : 0.0f;
      float w1a = (gl < 3) ? __ldg(W3 + (k0 + 8)*3 + gl) : 0.0f;
      float w1b = (gl < 3) ? __ldg(W3 + (k0 + 9)*3 + gl) : 0.0f;
      *(uint2*)(smem + OFF_W3F + (kk2*32 + tid)*8) =
          make_uint2(f16x2_of(w0a, w0b), f16x2_of(w1a, w1b));
    }
  }

  const int row_ = blockIdx.x * TPB + tid;
  const int row  = (row_ < nrows) ? row_ : (nrows - 1);   // clamp; keep all lanes active

  // ---- prologue: s1[j] = b1[j] + sensory . W1[3:64, j] -> f16x2, row-major temp ----
  {
    const float* srow = sens + (size_t)row * SENS;
    char* wtmp = smem + OFF_S1F + wid*4096;    // 32 rows x 128B per warp (temp, re-laid below)
    #pragma unroll
    for (int half = 0; half < 2; half++) {
      float4 acc[8];
      const float4* b1v = (const float4*)b1;
      #pragma unroll
      for (int q = 0; q < 8; q++) acc[q] = __ldg(b1v + half*8 + q);
      for (int s2 = 0; s2 < SENS; s2++) {
        float sv = __ldg(srow + s2);
        const float4* wr = (const float4*)(W1 + (3 + s2) * HID) + half*8;
        #pragma unroll
        for (int q = 0; q < 8; q++) {
          float4 w = __ldg(wr + q);
          acc[q].x = fmaf(sv, w.x, acc[q].x);
          acc[q].y = fmaf(sv, w.y, acc[q].y);
          acc[q].z = fmaf(sv, w.z, acc[q].z);
          acc[q].w = fmaf(sv, w.w, acc[q].w);
        }
      }
      #pragma unroll
      for (int q = 0; q < 8; q += 2) {
        uint4 pk;
        pk.x = f16x2_of(acc[q].x,   acc[q].y);
        pk.y = f16x2_of(acc[q].z,   acc[q].w);
        pk.z = f16x2_of(acc[q+1].x, acc[q+1].y);
        pk.w = f16x2_of(acc[q+1].z, acc[q+1].w);
        *(uint4*)(wtmp + lane*128 + (half*4 + (q>>1))*16) = pk;
      }
    }
  }
  __syncthreads();

  // gather s1 into D1-fragment layout (rows 16m+g, 16m+g+8; col-pair 4j+t)
  {
    u32 cfr[2][4][4];
    const char* wtmp = smem + OFF_S1F + wid*4096;
    #pragma unroll
    for (int m = 0; m < 2; m++)
      #pragma unroll
      for (int jp = 0; jp < 4; jp++)
        #pragma unroll
        for (int e = 0; e < 2; e++) {
          int j = 2*jp + e;
          cfr[m][jp][2*e + 0] = *(const u32*)(wtmp + (16*m + g    )*128 + (4*j + t)*4);
          cfr[m][jp][2*e + 1] = *(const u32*)(wtmp + (16*m + g + 8)*128 + (4*j + t)*4);
        }
    __syncthreads();
    #pragma unroll
    for (int m = 0; m < 2; m++)
      #pragma unroll
      for (int jp = 0; jp < 4; jp++)
        *(uint4*)(smem + OFF_S1F + (((m*4 + jp)*TPB) + tid)*16) =
            make_uint4(cfr[m][jp][0], cfr[m][jp][1], cfr[m][jp][2], cfr[m][jp][3]);
  }
  __syncthreads();

  // loop-invariant b2 C-init values (16 regs)
  float b2lo[8], b2hi[8];
  #pragma unroll
  for (int q = 0; q < 4; q++) {
    float4 bq = sB2Fq[t*4 + q];
    b2lo[2*q]   = bq.x;  b2hi[2*q]   = bq.y;
    b2lo[2*q+1] = bq.z;  b2hi[2*q+1] = bq.w;
  }
  float b3r[3] = {__ldg(b3 + 0), __ldg(b3 + 1), __ldg(b3 + 2)};
  const float sc = __ldg(scale);

  // ---- integrate ----
  float y0 = __ldg(pad0 + (size_t)row*3 + 0);
  float y1 = __ldg(pad0 + (size_t)row*3 + 1);
  float y2 = __ldg(pad0 + (size_t)row*3 + 2);
  const float h = 1.0f / (float)NSTEPS;

  const u32 xw    = smem_base + OFF_X   + wid * 512;   // 32 rows x 16B
  const u32 warpS = smem_base + OFF_STG + wid * 512;   // 32 x 16B (result staging)
  float kst[6][3];

  #pragma unroll 1
  for (int st = 0; st < NSTEPS; st++) {
    float t0 = (float)st * h;

    #pragma unroll 1
    for (int s = 0; s < 6; s++) {
      float ys0 = y0, ys1 = y1, ys2 = y2;
      #pragma unroll
      for (int m = 0; m < 5; m++) {
        if (m < s) {
          float a = h * c_A[s][m];
          ys0 = fmaf(a, kst[m][0], ys0);
          ys1 = fmaf(a, kst[m][1], ys1);
          ys2 = fmaf(a, kst[m][2], ys2);
        }
      }
      float ts = fmaf(c_C[s], h, t0);

      // ---- pack x = [y0,y1,y2,t] (f16, k-pad 8) and load A-fragments ----
      {
        u32 x01 = f16x2_of(ys0, ys1);
        u32 x23 = f16x2_of(ys2, ts);
        asm volatile("st.shared.v4.b32 [%0], {%1,%2,%3,%4};"
                     :: "r"(xw + (u32)(lane*16)), "r"(x01), "r"(x23), "r"(0u), "r"(0u) : "memory");
      }
      __syncwarp();
      u32 xa[4];
      ldmx2(xa[0], xa[1], xw + (u32)((lane & 15)*16));
      ldmx2(xa[2], xa[3], xw + (u32)((16 + (lane & 15))*16));

      // ---- fused layer1 (mma k8, C=s1) -> tanh2 -> layer2 (mma k16, C=b2 at kk=0) ----
      float d[2][8][4];
      #pragma unroll
      for (int kk = 0; kk < 4; kk++) {
        uint2 wb = *(const uint2*)(smem + OFF_W1B + (kk*32 + lane)*8);
        u32 hfr[2][4];
        #pragma unroll
        for (int m = 0; m < 2; m++) {
          uint4 sf = *(const uint4*)(smem + OFF_S1F + (((m*4 + kk)*TPB) + tid)*16);
          u32 p0, p1, p2, p3;
          mma_k8_f16(p0, p1, xa[2*m], xa[2*m+1], wb.x, sf.x, sf.y);
          mma_k8_f16(p2, p3, xa[2*m], xa[2*m+1], wb.y, sf.z, sf.w);
          hfr[m][0] = tanh2(p0);  hfr[m][1] = tanh2(p1);
          hfr[m][2] = tanh2(p2);  hfr[m][3] = tanh2(p3);
        }
        #pragma unroll
        for (int jp2 = 0; jp2 < 4; jp2++) {
          uint4 Bq = *(const uint4*)(smem + OFF_BF + (((kk*4 + jp2)*32) + lane)*16);
          int j = 2*jp2;
          if (kk == 0) {
            #pragma unroll
            for (int m = 0; m < 2; m++) {
              mmaf16_c(d[m][j][0], d[m][j][1], d[m][j][2], d[m][j][3],
                       hfr[m][0], hfr[m][1], hfr[m][2], hfr[m][3], Bq.x, Bq.y,
                       b2lo[j], b2hi[j], b2lo[j], b2hi[j]);
              mmaf16_c(d[m][j+1][0], d[m][j+1][1], d[m][j+1][2], d[m][j+1][3],
                       hfr[m][0], hfr[m][1], hfr[m][2], hfr[m][3], Bq.z, Bq.w,
                       b2lo[j+1], b2hi[j+1], b2lo[j+1], b2hi[j+1]);
            }
          } else {
            #pragma unroll
            for (int m = 0; m < 2; m++) {
              mmaf16(d[m][j][0], d[m][j][1], d[m][j][2], d[m][j][3],
                     hfr[m][0], hfr[m][1], hfr[m][2], hfr[m][3], Bq.x, Bq.y);
              mmaf16(d[m][j+1][0], d[m][j+1][1], d[m][j+1][2], d[m][j+1][3],
                     hfr[m][0], hfr[m][1], hfr[m][2], hfr[m][3], Bq.z, Bq.w);
            }
          }
        }
      }

      // ---- epilogue: tanh2(D) feeds layer-3 MMA directly (D-frag == A-frag layout) ----
      float d2[2][4];
      #pragma unroll
      for (int m = 0; m < 2; m++) { d2[m][0]=0.f; d2[m][1]=0.f; d2[m][2]=0.f; d2[m][3]=0.f; }

      #pragma unroll
      for (int m = 0; m < 2; m++) {
        #pragma unroll
        for (int kk2 = 0; kk2 < 4; kk2++) {
          int j0 = 2*kk2;
          u32 a0v = tanh2(f16x2_of(d[m][j0  ][0], d[m][j0  ][1]));
          u32 a1v = tanh2(f16x2_of(d[m][j0  ][2], d[m][j0  ][3]));
          u32 a2v = tanh2(f16x2_of(d[m][j0+1][0], d[m][j0+1][1]));
          u32 a3v = tanh2(f16x2_of(d[m][j0+1][2], d[m][j0+1][3]));
          uint2 bw = *(const uint2*)(smem + OFF_W3F + (kk2*32 + lane)*8);
          mmaf16(d2[m][0], d2[m][1], d2[m][2], d2[m][3],
                 a0v, a1v, a2v, a3v, bw.x, bw.y);
        }
      }

      // ---- route D2 (cols 0..2) to row owners via staging buffer ----
      if (t == 0) {           // holds cols 0,1
        #pragma unroll
        for (int m = 0; m < 2; m++) {
          asm volatile("st.shared.v2.f32 [%0], {%1,%2};"
                       :: "r"(warpS + (u32)((16*m + g)*16)), "f"(d2[m][0]), "f"(d2[m][1]) : "memory");
          asm volatile("st.shared.v2.f32 [%0], {%1,%2};"
                       :: "r"(warpS + (u32)((16*m + g + 8)*16)), "f"(d2[m][2]), "f"(d2[m][3]) : "memory");
        }
      } else if (t == 1) {    // holds col 2 (slot 0 of its pair)
        #pragma unroll
        for (int m = 0; m < 2; m++) {
          asm volatile("st.shared.f32 [%0], %1;"
                       :: "r"(warpS + (u32)((16*m + g)*16 + 8)), "f"(d2[m][0]) : "memory");
          asm volatile("st.shared.f32 [%0], %1;"
                       :: "r"(warpS + (u32)((16*m + g + 8)*16 + 8)), "f"(d2[m][2]) : "memory");
        }
      }
      __syncwarp();
      float v0, v1, v2w, v3w;
      asm volatile("ld.shared.v4.f32 {%0,%1,%2,%3}, [%4];"
                   : "=f"(v0), "=f"(v1), "=f"(v2w), "=f"(v3w)
                   : "r"(warpS + (u32)(lane*16)));
      kst[s][0] = ftanh(v0  + b3r[0]) * sc;
      kst[s][1] = ftanh(v1  + b3r[1]) * sc;
      kst[s][2] = ftanh(v2w + b3r[2]) * sc;
      // next staging write is behind the next eval's x-pack __syncwarp
    }

    #pragma unroll
    for (int m = 0; m < 6; m++) {
      float bm = h * c_Bw[m];
      y0 = fmaf(bm, kst[m][0], y0);
      y1 = fmaf(bm, kst[m][1], y1);
      y2 = fmaf(bm, kst[m][2], y2);
    }
  }

  if (row_ < nrows) {
    out[(size_t)row*3 + 0] = y0;
    out[(size_t)row*3 + 1] = y1;
    out[(size_t)row*3 + 2] = y2;
  }
}

extern "C" void kernel_launch(void* const* d_in, const int* in_sizes, int n_in,
                              void* d_out, int out_size) {
  const float* pad0  = (const float*)d_in[0];
  const float* sens  = (const float*)d_in[1];
  const float* W1    = (const float*)d_in[2];
  const float* b1    = (const float*)d_in[3];
  const float* W2    = (const float*)d_in[4];
  const float* b2    = (const float*)d_in[5];
  const float* W3    = (const float*)d_in[6];
  const float* b3    = (const float*)d_in[7];
  const float* scale = (const float*)d_in[8];
  float* out = (float*)d_out;

  const int nrows = in_sizes[0] / 3;
  cudaFuncSetAttribute(ode_kernel, cudaFuncAttributeMaxDynamicSharedMemorySize, SMEM_BYTES);

  const int grid = (nrows + TPB - 1) / TPB;
  ode_kernel<<<grid, TPB, SMEM_BYTES>>>(pad0, sens, W1, b1, W2, b2, W3, b3, scale, out, nrows);
}

// round 17
// speedup vs baseline: 1.0648x; 1.0648x over previous
#include <cuda_runtime.h>
#include <cuda_bf16.h>

#define SENS 61
#define HID  64
#define NSTEPS 10
#define TPB  128

typedef unsigned long long u64;
typedef unsigned int u32;

// Dormand–Prince 5(4) tableau
__constant__ float c_A[6][5] = {
  {0.f, 0.f, 0.f, 0.f, 0.f},
  {(float)(1.0/5.0), 0.f, 0.f, 0.f, 0.f},
  {(float)(3.0/40.0), (float)(9.0/40.0), 0.f, 0.f, 0.f},
  {(float)(44.0/45.0), (float)(-56.0/15.0), (float)(32.0/9.0), 0.f, 0.f},
  {(float)(19372.0/6561.0), (float)(-25360.0/2187.0), (float)(64448.0/6561.0), (float)(-212.0/729.0), 0.f},
  {(float)(9017.0/3168.0), (float)(-355.0/33.0), (float)(46732.0/5247.0), (float)(49.0/176.0), (float)(-5103.0/18656.0)}
};
__constant__ float c_C[6] = {0.f, 0.2f, 0.3f, 0.8f, (float)(8.0/9.0), 1.f};
__constant__ float c_Bw[6] = {(float)(35.0/384.0), 0.f, (float)(500.0/1113.0),
                              (float)(125.0/192.0), (float)(-2187.0/6784.0), (float)(11.0/84.0)};

// ---- helpers ----
__device__ __forceinline__ float ftanh(float x) {
  float r; asm("tanh.approx.f32 %0, %1;" : "=f"(r) : "f"(x)); return r;
}
__device__ __forceinline__ u32 f16x2_of(float lo, float hi) {
  u32 r; asm("cvt.rn.f16x2.f32 %0, %1, %2;" : "=r"(r) : "f"(hi), "f"(lo)); return r; // upper=hi, lower=lo
}
__device__ __forceinline__ u32 tanh2(u32 x) {
  u32 r; asm("tanh.approx.f16x2 %0, %1;" : "=r"(r) : "r"(x)); return r;
}
__device__ __forceinline__ u32 smem_u32(const void* p) {
  u32 a; asm("{ .reg .u64 t; cvta.to.shared.u64 t, %1; cvt.u32.u64 %0, t; }" : "=r"(a) : "l"(p));
  return a;
}
__device__ __forceinline__ void ldmx2(u32& r0, u32& r1, u32 addr) {
  asm volatile("ldmatrix.sync.aligned.m8n8.x2.shared.b16 {%0,%1}, [%2];"
               : "=r"(r0), "=r"(r1) : "r"(addr));
}
// m16n8k8, f16 in/out: D = A*B + C  (C separate, f16x2 pairs)
__device__ __forceinline__ void mma_k8_f16(u32& d0, u32& d1,
                                           u32 a0, u32 a1, u32 b0, u32 c0, u32 c1) {
  asm volatile("mma.sync.aligned.m16n8k8.row.col.f16.f16.f16.f16 "
               "{%0,%1}, {%2,%3}, {%4}, {%5,%6};"
               : "=r"(d0), "=r"(d1)
               : "r"(a0), "r"(a1), "r"(b0), "r"(c0), "r"(c1));
}
// m16n8k16, f16 acc, in-place C=D
__device__ __forceinline__ void mma_k16_h(u32& d0, u32& d1,
                                          u32 a0, u32 a1, u32 a2, u32 a3, u32 b0, u32 b1) {
  asm volatile("mma.sync.aligned.m16n8k16.row.col.f16.f16.f16.f16 "
               "{%0,%1}, {%2,%3,%4,%5}, {%6,%7}, {%0,%1};"
               : "+r"(d0), "+r"(d1)
               : "r"(a0), "r"(a1), "r"(a2), "r"(a3), "r"(b0), "r"(b1));
}
// m16n8k16, f16 acc, separate C (accumulator init for free)
__device__ __forceinline__ void mma_k16_h_c(u32& d0, u32& d1,
                                            u32 a0, u32 a1, u32 a2, u32 a3, u32 b0, u32 b1,
                                            u32 c0, u32 c1) {
  asm volatile("mma.sync.aligned.m16n8k16.row.col.f16.f16.f16.f16 "
               "{%0,%1}, {%2,%3,%4,%5}, {%6,%7}, {%8,%9};"
               : "=r"(d0), "=r"(d1)
               : "r"(a0), "r"(a1), "r"(a2), "r"(a3), "r"(b0), "r"(b1), "r"(c0), "r"(c1));
}
// m16n8k16, f32 acc, in-place C=D (layer 3 keeps f32 accumulation)
__device__ __forceinline__ void mmaf16(float& d0, float& d1, float& d2, float& d3,
                                       u32 a0, u32 a1, u32 a2, u32 a3, u32 b0, u32 b1) {
  asm volatile("mma.sync.aligned.m16n8k16.row.col.f32.f16.f16.f32 "
               "{%0,%1,%2,%3}, {%4,%5,%6,%7}, {%8,%9}, {%0,%1,%2,%3};"
               : "+f"(d0), "+f"(d1), "+f"(d2), "+f"(d3)
               : "r"(a0), "r"(a1), "r"(a2), "r"(a3), "r"(b0), "r"(b1));
}

// smem byte offsets
#define OFF_X    0                          // 4 warps * 32 rows * 16B = 2048 (x = [y,t] f16, k-pad 8)
#define OFF_S1F  2048                       // uint4[8 (m*4+kk)][TPB] = 16384 (s1 in D1-fragment layout)
#define OFF_BF   (OFF_S1F + 16384)          // uint4[4 kk][4 jp][32 lane] = 8192 (W2 B-frags, f16)
#define OFF_W3F  (OFF_BF + 8192)            // uint2[4 kk2][32 lane] = 1024 (W3 B-frags, f16, N-pad 8)
#define OFF_W1B  (OFF_W3F + 1024)           // uint2[4 kk][32 lane] = 1024 (W1 y/t B-frags, k-pad 8)
#define OFF_STG  (OFF_W1B + 1024)           // 4 warps * 32 * 16B = 2048 (result staging)
#define SMEM_BYTES (OFF_STG + 2048)         // 30720

__global__ void __launch_bounds__(TPB, 4)
ode_kernel(const float* __restrict__ pad0, const float* __restrict__ sens,
           const float* __restrict__ W1, const float* __restrict__ b1,
           const float* __restrict__ W2, const float* __restrict__ b2,
           const float* __restrict__ W3, const float* __restrict__ b3,
           const float* __restrict__ scale, float* __restrict__ out, int nrows)
{
  extern __shared__ char smem[];
  const u32 smem_base = smem_u32(smem);
  const int tid  = threadIdx.x;
  const int lane = tid & 31;
  const int wid  = tid >> 5;
  const int g    = lane >> 2;     // fragment group id (row within 8)
  const int t    = lane & 3;      // thread-in-group (col pair)

  // ---- cooperative weight staging ----
  // W1 y/t B-fragments for m16n8k8 (k = [y0,y1,y2,t,0,0,0,0])
  if (tid < 32) {
    int gl = tid >> 2, tl = tid & 3;
    #pragma unroll
    for (int jp = 0; jp < 4; jp++) {
      u32 v[2];
      #pragma unroll
      for (int e = 0; e < 2; e++) {
        int n = 8*(2*jp + e) + gl;
        float wa = 0.f, wb = 0.f;
        if (tl == 0)      { wa = __ldg(W1 + 0*HID + n);  wb = __ldg(W1 + 1*HID + n);  }
        else if (tl == 1) { wa = __ldg(W1 + 2*HID + n);  wb = __ldg(W1 + 64*HID + n); }
        v[e] = f16x2_of(wa, wb);
      }
      *(uint2*)(smem + OFF_W1B + (jp*32 + tid)*8) = make_uint2(v[0], v[1]);
    }
  }
  // W2 B-fragments (f16), per-lane layout, one copy for all warps
  if (tid < 32) {
    int gl = tid >> 2, tl = tid & 3;
    #pragma unroll
    for (int kk = 0; kk < 4; kk++) {
      #pragma unroll
      for (int jp = 0; jp < 4; jp++) {
        u32 v[4];
        #pragma unroll
        for (int e = 0; e < 2; e++) {     // j = 2*jp + e
          int n = 8*(2*jp + e) + gl;
          int k0 = 16*kk + 2*tl;
          v[2*e + 0] = f16x2_of(__ldg(W2 + (k0    )*HID + n), __ldg(W2 + (k0 + 1)*HID + n));
          v[2*e + 1] = f16x2_of(__ldg(W2 + (k0 + 8)*HID + n), __ldg(W2 + (k0 + 9)*HID + n));
        }
        *(uint4*)(smem + OFF_BF + (((kk*4 + jp)*32) + tid)*16) = make_uint4(v[0], v[1], v[2], v[3]);
      }
    }
  }
  // W3 B-fragments (f16): 4 k-blocks of 16; B tile 16(k) x 8(n), n>=3 zero-padded
  if (tid < 32) {
    int gl = tid >> 2, tl = tid & 3;
    #pragma unroll
    for (int kk2 = 0; kk2 < 4; kk2++) {
      int k0 = kk2*16 + 2*tl;
      float w0a = (gl < 3) ? __ldg(W3 + (k0    )*3 + gl) : 0.0f;
      float w0b = (gl < 3) ? __ldg(W3 + (k0 + 1)*3 + gl) : 0.0f;
      float w1a = (gl < 3) ? __ldg(W3 + (k0 + 8)*3 + gl) : 0.0f;
      float w1b = (gl < 3) ? __ldg(W3 + (k0 + 9)*3 + gl) : 0.0f;
      *(uint2*)(smem + OFF_W3F + (kk2*32 + tid)*8) =
          make_uint2(f16x2_of(w0a, w0b), f16x2_of(w1a, w1b));
    }
  }

  const int row_ = blockIdx.x * TPB + tid;
  const int row  = (row_ < nrows) ? row_ : (nrows - 1);   // clamp; keep all lanes active

  // ---- prologue: s1[j] = b1[j] + sensory . W1[3:64, j] -> f16x2, row-major temp ----
  {
    const float* srow = sens + (size_t)row * SENS;
    char* wtmp = smem + OFF_S1F + wid*4096;    // 32 rows x 128B per warp (temp, re-laid below)
    #pragma unroll
    for (int half = 0; half < 2; half++) {
      float4 acc[8];
      const float4* b1v = (const float4*)b1;
      #pragma unroll
      for (int q = 0; q < 8; q++) acc[q] = __ldg(b1v + half*8 + q);
      for (int s2 = 0; s2 < SENS; s2++) {
        float sv = __ldg(srow + s2);
        const float4* wr = (const float4*)(W1 + (3 + s2) * HID) + half*8;
        #pragma unroll
        for (int q = 0; q < 8; q++) {
          float4 w = __ldg(wr + q);
          acc[q].x = fmaf(sv, w.x, acc[q].x);
          acc[q].y = fmaf(sv, w.y, acc[q].y);
          acc[q].z = fmaf(sv, w.z, acc[q].z);
          acc[q].w = fmaf(sv, w.w, acc[q].w);
        }
      }
      #pragma unroll
      for (int q = 0; q < 8; q += 2) {
        uint4 pk;
        pk.x = f16x2_of(acc[q].x,   acc[q].y);
        pk.y = f16x2_of(acc[q].z,   acc[q].w);
        pk.z = f16x2_of(acc[q+1].x, acc[q+1].y);
        pk.w = f16x2_of(acc[q+1].z, acc[q+1].w);
        *(uint4*)(wtmp + lane*128 + (half*4 + (q>>1))*16) = pk;
      }
    }
  }
  __syncthreads();

  // gather s1 into D1-fragment layout (rows 16m+g, 16m+g+8; col-pair 4j+t)
  {
    u32 cfr[2][4][4];
    const char* wtmp = smem + OFF_S1F + wid*4096;
    #pragma unroll
    for (int m = 0; m < 2; m++)
      #pragma unroll
      for (int jp = 0; jp < 4; jp++)
        #pragma unroll
        for (int e = 0; e < 2; e++) {
          int j = 2*jp + e;
          cfr[m][jp][2*e + 0] = *(const u32*)(wtmp + (16*m + g    )*128 + (4*j + t)*4);
          cfr[m][jp][2*e + 1] = *(const u32*)(wtmp + (16*m + g + 8)*128 + (4*j + t)*4);
        }
    __syncthreads();
    #pragma unroll
    for (int m = 0; m < 2; m++)
      #pragma unroll
      for (int jp = 0; jp < 4; jp++)
        *(uint4*)(smem + OFF_S1F + (((m*4 + jp)*TPB) + tid)*16) =
            make_uint4(cfr[m][jp][0], cfr[m][jp][1], cfr[m][jp][2], cfr[m][jp][3]);
  }
  __syncthreads();

  // loop-invariant b2 C-init (f16x2 pairs; rows g and g+8 share col values)
  u32 b2pk[8];
  #pragma unroll
  for (int j = 0; j < 8; j++)
    b2pk[j] = f16x2_of(__ldg(b2 + 8*j + 2*t), __ldg(b2 + 8*j + 2*t + 1));
  float b3r[3] = {__ldg(b3 + 0), __ldg(b3 + 1), __ldg(b3 + 2)};
  const float sc = __ldg(scale);

  // ---- integrate ----
  float y0 = __ldg(pad0 + (size_t)row*3 + 0);
  float y1 = __ldg(pad0 + (size_t)row*3 + 1);
  float y2 = __ldg(pad0 + (size_t)row*3 + 2);
  const float h = 1.0f / (float)NSTEPS;

  const u32 xw    = smem_base + OFF_X   + wid * 512;   // 32 rows x 16B
  const u32 warpS = smem_base + OFF_STG + wid * 512;   // 32 x 16B (result staging)
  float kst[6][3];

  #pragma unroll 1
  for (int st = 0; st < NSTEPS; st++) {
    float t0 = (float)st * h;

    #pragma unroll 1
    for (int s = 0; s < 6; s++) {
      float ys0 = y0, ys1 = y1, ys2 = y2;
      #pragma unroll
      for (int m = 0; m < 5; m++) {
        if (m < s) {
          float a = h * c_A[s][m];
          ys0 = fmaf(a, kst[m][0], ys0);
          ys1 = fmaf(a, kst[m][1], ys1);
          ys2 = fmaf(a, kst[m][2], ys2);
        }
      }
      float ts = fmaf(c_C[s], h, t0);

      // ---- pack x = [y0,y1,y2,t] (f16, k-pad 8) and load A-fragments ----
      {
        u32 x01 = f16x2_of(ys0, ys1);
        u32 x23 = f16x2_of(ys2, ts);
        asm volatile("st.shared.v4.b32 [%0], {%1,%2,%3,%4};"
                     :: "r"(xw + (u32)(lane*16)), "r"(x01), "r"(x23), "r"(0u), "r"(0u) : "memory");
      }
      __syncwarp();
      u32 xa[4];
      ldmx2(xa[0], xa[1], xw + (u32)((lane & 15)*16));
      ldmx2(xa[2], xa[3], xw + (u32)((16 + (lane & 15))*16));

      // ---- fused layer1 (mma k8, C=s1) -> tanh2 -> layer2 (mma k16, f16 acc, C=b2 at kk=0) ----
      u32 d[2][8][2];
      #pragma unroll
      for (int kk = 0; kk < 4; kk++) {
        uint2 wb = *(const uint2*)(smem + OFF_W1B + (kk*32 + lane)*8);
        u32 hfr[2][4];
        #pragma unroll
        for (int m = 0; m < 2; m++) {
          uint4 sf = *(const uint4*)(smem + OFF_S1F + (((m*4 + kk)*TPB) + tid)*16);
          u32 p0, p1, p2, p3;
          mma_k8_f16(p0, p1, xa[2*m], xa[2*m+1], wb.x, sf.x, sf.y);
          mma_k8_f16(p2, p3, xa[2*m], xa[2*m+1], wb.y, sf.z, sf.w);
          hfr[m][0] = tanh2(p0);  hfr[m][1] = tanh2(p1);
          hfr[m][2] = tanh2(p2);  hfr[m][3] = tanh2(p3);
        }
        #pragma unroll
        for (int jp2 = 0; jp2 < 4; jp2++) {
          uint4 Bq = *(const uint4*)(smem + OFF_BF + (((kk*4 + jp2)*32) + lane)*16);
          int j = 2*jp2;
          if (kk == 0) {
            #pragma unroll
            for (int m = 0; m < 2; m++) {
              mma_k16_h_c(d[m][j][0], d[m][j][1],
                          hfr[m][0], hfr[m][1], hfr[m][2], hfr[m][3], Bq.x, Bq.y,
                          b2pk[j], b2pk[j]);
              mma_k16_h_c(d[m][j+1][0], d[m][j+1][1],
                          hfr[m][0], hfr[m][1], hfr[m][2], hfr[m][3], Bq.z, Bq.w,
                          b2pk[j+1], b2pk[j+1]);
            }
          } else {
            #pragma unroll
            for (int m = 0; m < 2; m++) {
              mma_k16_h(d[m][j][0], d[m][j][1],
                        hfr[m][0], hfr[m][1], hfr[m][2], hfr[m][3], Bq.x, Bq.y);
              mma_k16_h(d[m][j+1][0], d[m][j+1][1],
                        hfr[m][0], hfr[m][1], hfr[m][2], hfr[m][3], Bq.z, Bq.w);
            }
          }
        }
      }

      // ---- epilogue: tanh2(D) IS the layer-3 A-fragment (no cvts at all) ----
      float d2[2][4];
      #pragma unroll
      for (int m = 0; m < 2; m++) { d2[m][0]=0.f; d2[m][1]=0.f; d2[m][2]=0.f; d2[m][3]=0.f; }

      #pragma unroll
      for (int m = 0; m < 2; m++) {
        #pragma unroll
        for (int kk2 = 0; kk2 < 4; kk2++) {
          int j0 = 2*kk2;
          u32 a0v = tanh2(d[m][j0  ][0]);
          u32 a1v = tanh2(d[m][j0  ][1]);
          u32 a2v = tanh2(d[m][j0+1][0]);
          u32 a3v = tanh2(d[m][j0+1][1]);
          uint2 bw = *(const uint2*)(smem + OFF_W3F + (kk2*32 + lane)*8);
          mmaf16(d2[m][0], d2[m][1], d2[m][2], d2[m][3],
                 a0v, a1v, a2v, a3v, bw.x, bw.y);
        }
      }

      // ---- route D2 (cols 0..2) to row owners via staging buffer ----
      if (t == 0) {           // holds cols 0,1
        #pragma unroll
        for (int m = 0; m < 2; m++) {
          asm volatile("st.shared.v2.f32 [%0], {%1,%2};"
                       :: "r"(warpS + (u32)((16*m + g)*16)), "f"(d2[m][0]), "f"(d2[m][1]) : "memory");
          asm volatile("st.shared.v2.f32 [%0], {%1,%2};"
                       :: "r"(warpS + (u32)((16*m + g + 8)*16)), "f"(d2[m][2]), "f"(d2[m][3]) : "memory");
        }
      } else if (t == 1) {    // holds col 2 (slot 0 of its pair)
        #pragma unroll
        for (int m = 0; m < 2; m++) {
          asm volatile("st.shared.f32 [%0], %1;"
                       :: "r"(warpS + (u32)((16*m + g)*16 + 8)), "f"(d2[m][0]) : "memory");
          asm volatile("st.shared.f32 [%0], %1;"
                       :: "r"(warpS + (u32)((16*m + g + 8)*16 + 8)), "f"(d2[m][2]) : "memory");
        }
      }
      __syncwarp();
      float v0, v1, v2w, v3w;
      asm volatile("ld.shared.v4.f32 {%0,%1,%2,%3}, [%4];"
                   : "=f"(v0), "=f"(v1), "=f"(v2w), "=f"(v3w)
                   : "r"(warpS + (u32)(lane*16)));
      kst[s][0] = ftanh(v0  + b3r[0]) * sc;
      kst[s][1] = ftanh(v1  + b3r[1]) * sc;
      kst[s][2] = ftanh(v2w + b3r[2]) * sc;
      // next staging write is behind the next eval's x-pack __syncwarp
    }

    #pragma unroll
    for (int m = 0; m < 6; m++) {
      float bm = h * c_Bw[m];
      y0 = fmaf(bm, kst[m][0], y0);
      y1 = fmaf(bm, kst[m][1], y1);
      y2 = fmaf(bm, kst[m][2], y2);
    }
  }

  if (row_ < nrows) {
    out[(size_t)row*3 + 0] = y0;
    out[(size_t)row*3 + 1] = y1;
    out[(size_t)row*3 + 2] = y2;
  }
}

extern "C" void kernel_launch(void* const* d_in, const int* in_sizes, int n_in,
                              void* d_out, int out_size) {
  const float* pad0  = (const float*)d_in[0];
  const float* sens  = (const float*)d_in[1];
  const float* W1    = (const float*)d_in[2];
  const float* b1    = (const float*)d_in[3];
  const float* W2    = (const float*)d_in[4];
  const float* b2    = (const float*)d_in[5];
  const float* W3    = (const float*)d_in[6];
  const float* b3    = (const float*)d_in[7];
  const float* scale = (const float*)d_in[8];
  float* out = (float*)d_out;

  const int nrows = in_sizes[0] / 3;
  cudaFuncSetAttribute(ode_kernel, cudaFuncAttributeMaxDynamicSharedMemorySize, SMEM_BYTES);

  const int grid = (nrows + TPB - 1) / TPB;
  ode_kernel<<<grid, TPB, SMEM_BYTES>>>(pad0, sens, W1, b1, W2, b2, W3, b3, scale, out, nrows);
}